// round 6
// baseline (speedup 1.0000x reference)
#include <cuda_runtime.h>
#include <cstdint>

#define BATCH 4
#define NSEQ  1024
#define DDIM  128
#define HDIM  64
#define ROWS  (BATCH*NSEQ)
#define PAD   68   // row stride 272B = 17 x 16B granules (odd) -> conflict-free strided LDS.128

// Scratch (device globals: no allocation allowed)
__device__ float g_U[ROWS*HDIM];
__device__ float g_V[ROWS*HDIM];
__device__ float g_DU[ROWS];
__device__ float g_DV[ROWS];

// tanh(x) = 1 - 2/(exp2(2x/ln2)+1); ex2/rcp.approx abs err ~1e-6 (<< 1e-3 budget)
__device__ __forceinline__ float fast_tanh(float x){
    float e, r;
    asm("ex2.approx.f32 %0, %1;" : "=f"(e) : "f"(x * 2.88539008f));
    asm("rcp.approx.f32 %0, %1;" : "=f"(r) : "f"(e + 1.0f));
    return fmaf(-2.0f, r, 1.0f);
}

// ---------------------------------------------------------------------------
// Kernel 1: per-row u = emb@Wa, v = emb@Wb + b1, du = w2.u, dv = w2.v
// 8 rows per 128-thread block; thread t owns output column (t&63) of half (t>>6)
// ---------------------------------------------------------------------------
__global__ __launch_bounds__(128) void k_pre(const float* __restrict__ emb,
                                             const float* __restrict__ W1,
                                             const float* __restrict__ b1,
                                             const float* __restrict__ W2){
    int row0 = blockIdx.x * 8;
    __shared__ float se[8][DDIM];
    __shared__ float sp[8][128];
    int t = threadIdx.x;

    const float4* g4 = (const float4*)(emb + (size_t)row0 * DDIM);
    float4* s4 = (float4*)&se[0][0];
    s4[t]       = g4[t];
    s4[t + 128] = g4[t + 128];
    __syncthreads();

    int h    = t & 63;
    int half = t >> 6;                               // 0 -> u (Wa), 1 -> v (Wb)
    const float* wcol = W1 + half*(DDIM*HDIM) + h;   // W1[(half*128+d)*64 + h]

    float acc[8];
    #pragma unroll
    for (int r = 0; r < 8; r++) acc[r] = 0.f;

    #pragma unroll 8
    for (int d = 0; d < DDIM; d++){
        float w = __ldg(wcol + d*HDIM);
        #pragma unroll
        for (int r = 0; r < 8; r++) acc[r] = fmaf(se[r][d], w, acc[r]);
    }

    float bb  = half ? __ldg(b1 + h) : 0.0f;
    float w2h = __ldg(W2 + h);
    #pragma unroll
    for (int r = 0; r < 8; r++){
        float a = acc[r] + bb;
        if (half) g_V[(row0+r)*HDIM + h] = a;
        else      g_U[(row0+r)*HDIM + h] = a;
        sp[r][t] = a * w2h;
    }
    __syncthreads();

    if (t < 16){
        int r = t >> 1, hf = t & 1;
        float s = 0.f;
        #pragma unroll 8
        for (int k = 0; k < 64; k++) s += sp[r][hf*64 + k];
        if (hf) g_DV[row0+r] = s; else g_DU[row0+r] = s;
    }
}

// ---------------------------------------------------------------------------
// One directed 64x64 block: out16[a*4+c] = tanh(0.5*(du_i + dv_j + sum_h w_h*|u_i+v_j|) + b2)
// with i-row = uLane + 16a, j-row = vLane + 16c (within the staged tiles).
// Inner loop packed f32x2 along h: per (pair, 2h): ADD2 + 2xLOP3 + FMA2.
// ---------------------------------------------------------------------------
__device__ __forceinline__ void pair_block(const float* __restrict__ uB,
                                           const float* __restrict__ vB,
                                           const float* __restrict__ sW,
                                           const float* __restrict__ dU,
                                           const float* __restrict__ dV,
                                           int uLane, int vLane, float bb,
                                           float out16[16]){
    unsigned long long acc[16];
    #pragma unroll
    for (int i = 0; i < 16; i++) acc[i] = 0ull;

    const float* pu = uB + uLane*PAD;
    const float* pv = vB + vLane*PAD;

    #pragma unroll 2
    for (int h = 0; h < HDIM; h += 4){
        unsigned long long w0 = *(const unsigned long long*)&sW[h];
        unsigned long long w1 = *(const unsigned long long*)&sW[h+2];
        unsigned long long ua0[4], ua1[4], vc0[4], vc1[4];
        #pragma unroll
        for (int a = 0; a < 4; a++){
            ulonglong2 tt = *(const ulonglong2*)&pu[(16*a)*PAD + h];
            ua0[a] = tt.x; ua1[a] = tt.y;
        }
        #pragma unroll
        for (int c = 0; c < 4; c++){
            ulonglong2 tt = *(const ulonglong2*)&pv[(16*c)*PAD + h];
            vc0[c] = tt.x; vc1[c] = tt.y;
        }
        #pragma unroll
        for (int a = 0; a < 4; a++){
            #pragma unroll
            for (int c = 0; c < 4; c++){
                unsigned long long t0, t1;
                asm("add.rn.f32x2 %0, %1, %2;" : "=l"(t0) : "l"(ua0[a]), "l"(vc0[c]));
                t0 &= 0x7fffffff7fffffffULL;           // packed |.| (alu pipe)
                asm("fma.rn.f32x2 %0, %1, %2, %3;"
                    : "=l"(acc[a*4+c]) : "l"(w0), "l"(t0), "l"(acc[a*4+c]));
                asm("add.rn.f32x2 %0, %1, %2;" : "=l"(t1) : "l"(ua1[a]), "l"(vc1[c]));
                t1 &= 0x7fffffff7fffffffULL;
                asm("fma.rn.f32x2 %0, %1, %2, %3;"
                    : "=l"(acc[a*4+c]) : "l"(w1), "l"(t1), "l"(acc[a*4+c]));
            }
        }
    }

    #pragma unroll
    for (int a = 0; a < 4; a++){
        float du = dU[uLane + 16*a];
        #pragma unroll
        for (int c = 0; c < 4; c++){
            unsigned long long v = acc[a*4+c];
            float lo = __uint_as_float((unsigned int)v);
            float hi = __uint_as_float((unsigned int)(v >> 32));
            float dot = 0.5f*(du + dV[vLane + 16*c] + lo + hi);
            out16[a*4+c] = fast_tanh(dot + bb);
        }
    }
}

// ---------------------------------------------------------------------------
// Kernel 2 (fused pair + symmetrize): one CTA per unordered 64x64 tile pair
// {I,J} (136 pairs per batch). Phase 1: s1 = scores of block (I,J). Phase 2:
// s2 = block (J,I) with mirrored operand roles; val = -0.5*(s1 + s2^T) is the
// final value for tile (I,J), and its transpose fills tile (J,I).
// Tile (I,J) written from registers (coalesced in tx); tile (J,I) staged
// through smem (pitch 65) for coalesced stores.
// ---------------------------------------------------------------------------
__global__ __launch_bounds__(256) void k_pairsym(const float* __restrict__ W2,
                                                 const float* __restrict__ b2,
                                                 float* __restrict__ out){
    extern __shared__ float sm[];
    float* sUa  = sm;                  // U rows of tile I
    float* sVa  = sm + 1*64*PAD;       // V rows of tile I
    float* sUb  = sm + 2*64*PAD;       // U rows of tile J
    float* sVb  = sm + 3*64*PAD;       // V rows of tile J
    float* sDUa = sm + 4*64*PAD;
    float* sDVa = sDUa + 64;
    float* sDUb = sDVa + 64;
    float* sDVb = sDUb + 64;
    float* sW   = sDVb + 64;
    float* sS   = sUa;                 // 64x65 transpose staging (reuses sUa)

    int bid  = blockIdx.x;
    int b    = bid / 136;
    int p    = bid % 136;
    int ti = 0;
    while (p >= 16 - ti){ p -= 16 - ti; ti++; }
    int tj = ti + p;                   // 0 <= ti <= tj < 16

    int tid = threadIdx.x;
    int tx = tid & 15, ty = tid >> 4;

    int rI = b*NSEQ + ti*64;
    int rJ = b*NSEQ + tj*64;

    for (int k = tid; k < 64*16; k += 256){
        int r = k >> 4, q = k & 15;
        *(float4*)&sUa[r*PAD + q*4] = *(const float4*)&g_U[(size_t)(rI + r)*HDIM + q*4];
        *(float4*)&sVa[r*PAD + q*4] = *(const float4*)&g_V[(size_t)(rI + r)*HDIM + q*4];
        *(float4*)&sUb[r*PAD + q*4] = *(const float4*)&g_U[(size_t)(rJ + r)*HDIM + q*4];
        *(float4*)&sVb[r*PAD + q*4] = *(const float4*)&g_V[(size_t)(rJ + r)*HDIM + q*4];
    }
    if (tid < 64){
        sDUa[tid] = g_DU[rI + tid];
        sDVa[tid] = g_DV[rI + tid];
        sDUb[tid] = g_DU[rJ + tid];
        sDVb[tid] = g_DV[rJ + tid];
        sW[tid]   = W2[tid];
    }
    __syncthreads();

    float bb = __ldg(b2);

    // phase 1: block (I,J): i = rI + ty + 16a, j = rJ + tx + 16c
    float s1[16];
    pair_block(sUa, sVb, sW, sDUa, sDVb, ty, tx, bb, s1);
    // phase 2: block (J,I): i = rJ + tx + 16a', j = rI + ty + 16c'
    float s2[16];
    pair_block(sUb, sVa, sW, sDUb, sDVa, tx, ty, bb, s2);

    // transpose partner of s1[a*4+c] = f(rI+ty+16a, rJ+tx+16c) is
    // f(rJ+tx+16c, rI+ty+16a) = s2[c*4+a]
    float val[16];
    #pragma unroll
    for (int a = 0; a < 4; a++)
        #pragma unroll
        for (int c = 0; c < 4; c++)
            val[a*4+c] = -0.5f*(s1[a*4+c] + s2[c*4+a]);

    // tile (I,J): row rI+ty+16a, col tj*64+tx+16c (coalesced in tx)
    #pragma unroll
    for (int a = 0; a < 4; a++){
        size_t rowoff = (size_t)(b*NSEQ + ti*64 + ty + 16*a)*NSEQ + tj*64;
        #pragma unroll
        for (int c = 0; c < 4; c++)
            out[rowoff + tx + 16*c] = val[a*4+c];
    }

    if (ti != tj){
        __syncthreads();               // done reading sUa (phase 1 finished)
        #pragma unroll
        for (int a = 0; a < 4; a++)
            #pragma unroll
            for (int c = 0; c < 4; c++)
                sS[(ty + 16*a)*65 + (tx + 16*c)] = val[a*4+c];
        __syncthreads();
        // tile (J,I): row rJ+ty+16a, col ti*64+tx+16c = val^T = sS[col][row]
        #pragma unroll
        for (int a = 0; a < 4; a++){
            size_t rowoff = (size_t)(b*NSEQ + tj*64 + ty + 16*a)*NSEQ + ti*64;
            #pragma unroll
            for (int c = 0; c < 4; c++)
                out[rowoff + tx + 16*c] = sS[(tx + 16*c)*65 + (ty + 16*a)];
        }
    }
}

// ---------------------------------------------------------------------------
extern "C" void kernel_launch(void* const* d_in, const int* in_sizes, int n_in,
                              void* d_out, int out_size){
    const float* emb = (const float*)d_in[0];
    const float* W1  = (const float*)d_in[1];
    const float* b1  = (const float*)d_in[2];
    const float* W2  = (const float*)d_in[3];
    const float* b2  = (const float*)d_in[4];
    float* out = (float*)d_out;

    int smem = (4*64*PAD + 5*64) * (int)sizeof(float);   // 70,912 B
    // unconditional every call (no static guards): not a stream op, capture-safe
    cudaFuncSetAttribute(k_pairsym,
                         cudaFuncAttributeMaxDynamicSharedMemorySize, smem);

    k_pre    <<<ROWS/8,    128>>>(emb, W1, b1, W2);
    k_pairsym<<<BATCH*136, 256, smem>>>(W2, b2, out);
}